// round 3
// baseline (speedup 1.0000x reference)
#include <cuda_runtime.h>
#include <math.h>

// InfoNCE loss, fused GEMM + online logsumexp.
// anchor [8192,512] f32, positive [8192,512] f32 -> scalar f32 mean loss.

#define NB 8192
#define ND 512
#define SCALE 10.0f   // 1 / TEMPERATURE

constexpr int BM = 64;    // rows per CTA
constexpr int BN = 128;   // cols per j-tile
constexpr int KT = 32;    // k-chunk
constexpr int AST = BM + 2;   // u64 stride (pad keeps 16B alignment of frag loads)
constexpr int BST = BN + 4;   // float stride (pad, multiple of 4 for float4 frags)

typedef unsigned long long u64;

__device__ float g_lse[NB];
__device__ float g_diag[NB];

__device__ __forceinline__ void ffma2(u64 &d, u64 a, u64 b) {
    // packed 2x fp32 FMA (sm_100+); ptxas never emits this from C++
    asm("fma.rn.f32x2 %0, %1, %2, %0;" : "+l"(d) : "l"(a), "l"(b));
}
__device__ __forceinline__ u64 dup2(float x) {
    unsigned u = __float_as_uint(x);
    return ((u64)u << 32) | (u64)u;
}

__global__ __launch_bounds__(256, 1)
void lse_kernel(const float* __restrict__ A, const float* __restrict__ P) {
    __shared__ u64   As2[KT][AST];   // A, k-major, pre-duplicated (a,a) pairs
    __shared__ float Bs [KT][BST];   // B, k-major

    const int tid = threadIdx.x;
    const int tx  = tid & 15;        // 16 col-threads
    const int ty  = tid >> 4;        // 16 row-threads
    const int bm0 = blockIdx.x * BM;

    // loader mappings
    const int ar = tid >> 2;          // 0..63  (A row)
    const int ak = (tid & 3) * 8;     // 0,8,16,24 (A k-offset, 8 floats each)
    const int br = tid >> 1;          // 0..127 (B row = col j)
    const int bk = (tid & 1) * 16;    // 0,16   (B k-offset, 16 floats each)

    float m_run[4], s_run[4];
#pragma unroll
    for (int r = 0; r < 4; r++) { m_run[r] = -3.0e38f; s_run[r] = 0.0f; }

    const float* agb = A + (bm0 + ar) * ND + ak;

    for (int jt = 0; jt < NB / BN; ++jt) {
        const int jn0 = jt * BN;
        const float* bgb = P + (jn0 + br) * ND + bk;

        u64 acc[4][4];
#pragma unroll
        for (int r = 0; r < 4; r++)
#pragma unroll
            for (int c = 0; c < 4; c++) acc[r][c] = 0ULL;

        // prefetch first k-chunk into registers
        float4 a0 = *(const float4*)(agb);
        float4 a1 = *(const float4*)(agb + 4);
        float4 b0 = *(const float4*)(bgb);
        float4 b1 = *(const float4*)(bgb + 4);
        float4 b2 = *(const float4*)(bgb + 8);
        float4 b3 = *(const float4*)(bgb + 12);

        for (int kc = 0; kc < ND; kc += KT) {
            __syncthreads();   // previous chunk's compute done
            {
                float av[8] = {a0.x,a0.y,a0.z,a0.w,a1.x,a1.y,a1.z,a1.w};
#pragma unroll
                for (int i = 0; i < 8; i++) As2[ak + i][ar] = dup2(av[i]);
                float bv[16] = {b0.x,b0.y,b0.z,b0.w, b1.x,b1.y,b1.z,b1.w,
                                b2.x,b2.y,b2.z,b2.w, b3.x,b3.y,b3.z,b3.w};
#pragma unroll
                for (int i = 0; i < 16; i++) Bs[bk + i][br] = bv[i];
            }
            __syncthreads();
            if (kc + KT < ND) {   // software-pipeline next chunk's global loads
                const float* ag = agb + kc + KT;
                const float* bg = bgb + kc + KT;
                a0 = *(const float4*)(ag);
                a1 = *(const float4*)(ag + 4);
                b0 = *(const float4*)(bg);
                b1 = *(const float4*)(bg + 4);
                b2 = *(const float4*)(bg + 8);
                b3 = *(const float4*)(bg + 12);
            }
#pragma unroll
            for (int k = 0; k < KT; k++) {
                // 4x LDS.128, 16x FFMA2 == 32 FMAs/thread/k
                ulonglong2 a01 = *(const ulonglong2*)&As2[k][ty * 4];
                ulonglong2 a23 = *(const ulonglong2*)&As2[k][ty * 4 + 2];
                ulonglong2 bA  = *(const ulonglong2*)&Bs[k][tx * 8];
                ulonglong2 bB  = *(const ulonglong2*)&Bs[k][tx * 8 + 4];
                u64 a_[4] = {a01.x, a01.y, a23.x, a23.y};
                u64 b_[4] = {bA.x, bA.y, bB.x, bB.y};
#pragma unroll
                for (int r = 0; r < 4; r++)
#pragma unroll
                    for (int c = 0; c < 4; c++)
                        ffma2(acc[r][c], a_[r], b_[c]);
            }
        }

        // fused online-logsumexp epilogue (row groups = 16 lanes sharing ty)
#pragma unroll
        for (int r = 0; r < 4; r++) {
            float cv[8];
#pragma unroll
            for (int c = 0; c < 4; c++) {
                cv[2*c]   = __uint_as_float((unsigned)(acc[r][c] & 0xffffffffULL)) * SCALE;
                cv[2*c+1] = __uint_as_float((unsigned)(acc[r][c] >> 32)) * SCALE;
            }
            float mt = cv[0];
#pragma unroll
            for (int i = 1; i < 8; i++) mt = fmaxf(mt, cv[i]);
#pragma unroll
            for (int off = 1; off < 16; off <<= 1)
                mt = fmaxf(mt, __shfl_xor_sync(0xffffffffu, mt, off));
            float mn = fmaxf(m_run[r], mt);
            float sadd = 0.0f;
            // skip exp work for tiles whose max is >30 below the running max:
            // contribution < 8192*e^-30 ~ 1e-9 relative. This kills ~all MUFU.
            if (mt > mn - 30.0f) {
#pragma unroll
                for (int i = 0; i < 8; i++) sadd += __expf(cv[i] - mn);
            }
#pragma unroll
            for (int off = 1; off < 16; off <<= 1)
                sadd += __shfl_xor_sync(0xffffffffu, sadd, off);
            s_run[r] = s_run[r] * __expf(m_run[r] - mn) + sadd;
            m_run[r] = mn;
        }
    }

    if (tx == 0) {
#pragma unroll
        for (int r = 0; r < 4; r++)
            g_lse[bm0 + ty * 4 + r] = m_run[r] + logf(s_run[r]);
    }
}

// diag[i] = <anchor_i, positive_i> * SCALE  — one warp per row, negligible cost
__global__ void diag_kernel(const float* __restrict__ A, const float* __restrict__ P) {
    int warp = (blockIdx.x * blockDim.x + threadIdx.x) >> 5;
    int lane = threadIdx.x & 31;
    if (warp >= NB) return;
    const float4* a4 = (const float4*)(A + (size_t)warp * ND);
    const float4* p4 = (const float4*)(P + (size_t)warp * ND);
    float s = 0.0f;
#pragma unroll
    for (int i = 0; i < 4; i++) {
        float4 a = a4[i * 32 + lane];
        float4 p = p4[i * 32 + lane];
        s += a.x * p.x + a.y * p.y + a.z * p.z + a.w * p.w;
    }
#pragma unroll
    for (int off = 16; off; off >>= 1) s += __shfl_xor_sync(0xffffffffu, s, off);
    if (lane == 0) g_diag[warp] = s * SCALE;
}

__global__ void reduce_kernel(float* __restrict__ out) {
    __shared__ float red[256];
    float s = 0.0f;
    for (int i = threadIdx.x; i < NB; i += 256)
        s += g_lse[i] - g_diag[i];
    red[threadIdx.x] = s;
    __syncthreads();
    for (int st = 128; st; st >>= 1) {
        if (threadIdx.x < st) red[threadIdx.x] += red[threadIdx.x + st];
        __syncthreads();
    }
    if (threadIdx.x == 0) out[0] = red[0] / (float)NB;
}

extern "C" void kernel_launch(void* const* d_in, const int* in_sizes, int n_in,
                              void* d_out, int out_size) {
    const float* anchor   = (const float*)d_in[0];
    const float* positive = (const float*)d_in[1];
    float* out = (float*)d_out;
    // same stream -> serialized; graph-capturable; no allocs (scratch is __device__)
    lse_kernel<<<NB / BM, 256>>>(anchor, positive);
    diag_kernel<<<NB / 8, 256>>>(anchor, positive);
    reduce_kernel<<<1, 256>>>(out);
}

// round 6
// speedup vs baseline: 4.7995x; 4.7995x over previous
#include <cuda_runtime.h>
#include <math.h>
#include <stdint.h>

// InfoNCE loss via mma.sync tf32 (legacy tensor path, not 'a'-gated) + fused online LSE.
// anchor [8192,512] f32, positive [8192,512] f32 -> scalar f32 mean loss.

#define NB 8192
#define ND 512
#define SCALE 10.0f   // 1/TEMPERATURE

constexpr int BM = 128;          // CTA rows
constexpr int BN = 128;          // CTA cols per j-tile
constexpr int KC = 32;           // k-chunk
constexpr int NHALF = NB / 2;    // 4096 cols per CTA (N split in 2 for SM fill)
constexpr int NT  = NHALF / BN;  // 32 j-tiles
constexpr int CPT = ND / KC;     // 16 k-chunks per tile
constexpr int TOTAL = NT * CPT;  // 512 chunks

constexpr int TILE_BYTES = BM * KC * 4;        // 16 KB (A and B tiles equal)
constexpr int NSTAGE = 4;
constexpr int SMEM_B0 = NSTAGE * TILE_BYTES;   // 64 KB
constexpr int SMEM_TOTAL = 2 * SMEM_B0;        // 128 KB

__device__ float g_Atf[NB * ND];   // tf32-rounded, k-pair-permuted copies
__device__ float g_Ptf[NB * ND];
// 4 partials per row: [halfN(2)][warpCol(2)][row] — fixes the R5 write race where
// both column-half warps clobbered one slot.
__device__ float g_pm[4 * NB];
__device__ float g_ps[4 * NB];
__device__ float g_diag[NB];

// ---------- helpers ----------
__device__ __forceinline__ uint32_t smem_u32(const void* p) {
    uint32_t a;
    asm("{ .reg .u64 t; cvta.to.shared.u64 t, %1; cvt.u32.u64 %0, t; }" : "=r"(a) : "l"(p));
    return a;
}
__device__ __forceinline__ uint64_t gaddr(const void* p) {
    uint64_t a;
    asm("cvta.to.global.u64 %0, %1;" : "=l"(a) : "l"(p));
    return a;
}
__device__ __forceinline__ void cp16(uint32_t dst, uint64_t src) {
    asm volatile("cp.async.cg.shared.global [%0], [%1], 16;" :: "r"(dst), "l"(src));
}
__device__ __forceinline__ void cp_commit() { asm volatile("cp.async.commit_group;" ::: "memory"); }
template <int N> __device__ __forceinline__ void cp_wait() {
    asm volatile("cp.async.wait_group %0;" :: "n"(N) : "memory");
}
__device__ __forceinline__ uint32_t tf32_rna(float x) {
    uint32_t r;
    asm("cvt.rna.tf32.f32 %0, %1;" : "=r"(r) : "f"(x));
    return r;
}
// D += A(m16k8,row) * B(k8n8,col) in tf32
__device__ __forceinline__ void mma_tf32(float* c, const uint32_t* a, const uint32_t* b) {
    asm volatile(
        "mma.sync.aligned.m16n8k8.row.col.f32.tf32.tf32.f32 "
        "{%0,%1,%2,%3}, {%4,%5,%6,%7}, {%8,%9}, {%0,%1,%2,%3};"
        : "+f"(c[0]), "+f"(c[1]), "+f"(c[2]), "+f"(c[3])
        : "r"(a[0]), "r"(a[1]), "r"(a[2]), "r"(a[3]), "r"(b[0]), "r"(b[1]));
}

// ---------- pre-pass: round to nearest tf32 + permute k within 8-groups ----------
// permuted order (0,4,1,5,2,6,3,7): frag pairs (c, c+4) become 8B-adjacent.
__global__ void prep_kernel(const float* __restrict__ A, const float* __restrict__ P) {
    int i = blockIdx.x * blockDim.x + threadIdx.x;    // one 8-float k-group
    if (i >= NB * ND / 8) return;
    float4 a0 = ((const float4*)A)[i * 2], a1 = ((const float4*)A)[i * 2 + 1];
    float4 p0 = ((const float4*)P)[i * 2], p1 = ((const float4*)P)[i * 2 + 1];
    uint4 oa0 = make_uint4(tf32_rna(a0.x), tf32_rna(a1.x), tf32_rna(a0.y), tf32_rna(a1.y));
    uint4 oa1 = make_uint4(tf32_rna(a0.z), tf32_rna(a1.z), tf32_rna(a0.w), tf32_rna(a1.w));
    uint4 op0 = make_uint4(tf32_rna(p0.x), tf32_rna(p1.x), tf32_rna(p0.y), tf32_rna(p1.y));
    uint4 op1 = make_uint4(tf32_rna(p0.z), tf32_rna(p1.z), tf32_rna(p0.w), tf32_rna(p1.w));
    ((uint4*)g_Atf)[i * 2] = oa0; ((uint4*)g_Atf)[i * 2 + 1] = oa1;
    ((uint4*)g_Ptf)[i * 2] = op0; ((uint4*)g_Ptf)[i * 2 + 1] = op1;
}

// ---------- main: tf32 mma GEMM + online logsumexp ----------
__global__ __launch_bounds__(256, 1)
void lse_mma_kernel() {
    extern __shared__ __align__(16) char smem[];
    const uint32_t sbase = smem_u32(smem);
    const int tid  = threadIdx.x;
    const int lane = tid & 31;
    const int w    = tid >> 5;
    const int warpRow = w & 3;     // 4 x 32 rows
    const int warpCol = w >> 2;    // 2 x 64 cols

    const int m0    = (blockIdx.x >> 1) * BM;
    const int halfN = blockIdx.x & 1;
    const int nbase = halfN * NHALF;

    // ---- loader geometry: thread handles one row-half (4 x 16B units) ----
    const int lr = tid >> 1;            // smem row 0..127
    const int lu = (tid & 1) * 4;       // first unit (of 8 per 128B row)
    const uint64_t aSrc0 = gaddr(g_Atf) + (uint64_t)(m0 + lr) * (ND * 4) + lu * 16;
    const uint64_t bSrc0 = gaddr(g_Ptf) + (uint64_t)(nbase + lr) * (ND * 4) + lu * 16;
    uint32_t aDst[4], bDst[4];
#pragma unroll
    for (int i = 0; i < 4; i++) {
        int u  = lu + i;
        int up = (((u >> 1) ^ (lr & 3)) << 1) | (u & 1);   // 32B-group XOR swizzle
        aDst[i] = sbase + lr * 128 + up * 16;
        bDst[i] = sbase + SMEM_B0 + lr * 128 + up * 16;
    }

    auto load_chunk = [&](int stage, int chunk) {
        const int jt = chunk >> 4, kc = chunk & 15;
        const uint64_t as = aSrc0 + kc * 128;
        const uint64_t bs = bSrc0 + (uint64_t)jt * (BN * ND * 4) + kc * 128;
        const uint32_t so = stage * TILE_BYTES;
#pragma unroll
        for (int i = 0; i < 4; i++) {
            cp16(aDst[i] + so, as + i * 16);
            cp16(bDst[i] + so, bs + i * 16);
        }
        cp_commit();
    };

    load_chunk(0, 0); load_chunk(1, 1); load_chunk(2, 2);

    // ---- fragment geometry ----
    const int qr = lane >> 2;        // 0..7 (row/col within 8-block)
    const int p  = lane & 3;         // frag pair index
    const int rm = qr & 3;           // swizzle row phase (block bases are mult of 8)
    uint32_t aOff[2][2];             // [mb][half] smem byte offsets (sans ks term)
#pragma unroll
    for (int mb = 0; mb < 2; mb++)
#pragma unroll
        for (int hh = 0; hh < 2; hh++) {
            int r = warpRow * 32 + mb * 16 + hh * 8 + qr;
            aOff[mb][hh] = r * 128 + p * 8;
        }
    uint32_t bOff[8];
#pragma unroll
    for (int nb = 0; nb < 8; nb++) {
        int n = warpCol * 64 + nb * 8 + qr;
        bOff[nb] = SMEM_B0 + n * 128 + p * 8;
    }

    float m_run[4], s_run[4];
#pragma unroll
    for (int i = 0; i < 4; i++) { m_run[i] = -3.0e38f; s_run[i] = 0.0f; }

    float c[2][8][4];

    for (int ch = 0; ch < TOTAL; ch++) {
        const int stage = ch & 3, kc = ch & 15;

        cp_wait<2>();
        __syncthreads();

        if (kc == 0) {
#pragma unroll
            for (int mb = 0; mb < 2; mb++)
#pragma unroll
                for (int nb = 0; nb < 8; nb++)
#pragma unroll
                    for (int q = 0; q < 4; q++) c[mb][nb][q] = 0.0f;
        }

        const uint32_t so = stage * TILE_BYTES;
#pragma unroll
        for (int ks = 0; ks < 4; ks++) {
            const uint32_t t = ((ks ^ rm) * 32) + so;
            uint32_t afr[2][4];
#pragma unroll
            for (int mb = 0; mb < 2; mb++) {
                float2 lo = *(const float2*)(smem + aOff[mb][0] + t);
                float2 hi = *(const float2*)(smem + aOff[mb][1] + t);
                afr[mb][0] = __float_as_uint(lo.x);
                afr[mb][1] = __float_as_uint(hi.x);
                afr[mb][2] = __float_as_uint(lo.y);
                afr[mb][3] = __float_as_uint(hi.y);
            }
#pragma unroll
            for (int nb = 0; nb < 8; nb++) {
                float2 b = *(const float2*)(smem + bOff[nb] + t);
                uint32_t bfr[2] = {__float_as_uint(b.x), __float_as_uint(b.y)};
#pragma unroll
                for (int mb = 0; mb < 2; mb++)
                    mma_tf32(c[mb][nb], afr[mb], bfr);
            }
        }

        // prefetch chunk ch+3 (its stage was consumed in iter ch-1; sync above protects)
        if (ch + 3 < TOTAL) load_chunk((ch + 3) & 3, ch + 3);
        else cp_commit();   // keep group count uniform

        // ---- register-only online-LSE epilogue at tile end ----
        if (kc == 15) {
#pragma unroll
            for (int ri = 0; ri < 4; ri++) {
                const int mb = ri >> 1, hh = ri & 1;
                float v[16];
#pragma unroll
                for (int nb = 0; nb < 8; nb++) {
                    v[2 * nb]     = c[mb][nb][hh * 2];
                    v[2 * nb + 1] = c[mb][nb][hh * 2 + 1];
                }
                float mx = v[0];
#pragma unroll
                for (int i = 1; i < 16; i++) mx = fmaxf(mx, v[i]);
                mx *= SCALE;
                // exp-skip: per-thread running max guards its own exps, no overflow
                if (mx >= m_run[ri] - 30.0f) {
                    const float mn = fmaxf(m_run[ri], mx);
                    float sa = 0.0f;
#pragma unroll
                    for (int i = 0; i < 16; i++) sa += __expf(fmaf(v[i], SCALE, -mn));
                    s_run[ri] = s_run[ri] * __expf(m_run[ri] - mn) + sa;
                    m_run[ri] = mn;
                }
            }
        }
    }

    // merge (m,s) across the 4-lane column group; write per-(halfN, warpCol) partials
#pragma unroll
    for (int ri = 0; ri < 4; ri++) {
        float m = m_run[ri], s = s_run[ri];
#pragma unroll
        for (int off = 1; off < 4; off <<= 1) {
            float mo = __shfl_xor_sync(0xffffffffu, m, off);
            float so = __shfl_xor_sync(0xffffffffu, s, off);
            float mn = fmaxf(m, mo);
            s = s * __expf(m - mn) + so * __expf(mo - mn);
            m = mn;
        }
        if ((lane & 3) == 0) {
            const int mb = ri >> 1, hh = ri & 1;
            const int row = m0 + warpRow * 32 + mb * 16 + hh * 8 + qr;
            const int slot = halfN * 2 + warpCol;      // 4 distinct slots per row
            g_pm[slot * NB + row] = m;
            g_ps[slot * NB + row] = s;
        }
    }
}

// diag[i] = <anchor_i, positive_i> * SCALE — full fp32 (matches reference)
__global__ void diag_kernel(const float* __restrict__ A, const float* __restrict__ P) {
    int warp = (blockIdx.x * blockDim.x + threadIdx.x) >> 5;
    int lane = threadIdx.x & 31;
    if (warp >= NB) return;
    const float4* a4 = (const float4*)(A + (size_t)warp * ND);
    const float4* p4 = (const float4*)(P + (size_t)warp * ND);
    float s = 0.0f;
#pragma unroll
    for (int i = 0; i < 4; i++) {
        float4 a = a4[i * 32 + lane];
        float4 p = p4[i * 32 + lane];
        s += a.x * p.x + a.y * p.y + a.z * p.z + a.w * p.w;
    }
#pragma unroll
    for (int off = 16; off; off >>= 1) s += __shfl_xor_sync(0xffffffffu, s, off);
    if (lane == 0) g_diag[warp] = s * SCALE;
}

__global__ void reduce_kernel(float* __restrict__ out) {
    __shared__ float red[256];
    float s = 0.0f;
    for (int i = threadIdx.x; i < NB; i += 256) {
        float m = g_pm[i];
#pragma unroll
        for (int q = 1; q < 4; q++) m = fmaxf(m, g_pm[q * NB + i]);
        float se = 0.0f;
#pragma unroll
        for (int q = 0; q < 4; q++) se += g_ps[q * NB + i] * __expf(g_pm[q * NB + i] - m);
        s += m + logf(se) - g_diag[i];
    }
    red[threadIdx.x] = s;
    __syncthreads();
    for (int st = 128; st; st >>= 1) {
        if (threadIdx.x < st) red[threadIdx.x] += red[threadIdx.x + st];
        __syncthreads();
    }
    if (threadIdx.x == 0) out[0] = red[0] / (float)NB;
}

extern "C" void kernel_launch(void* const* d_in, const int* in_sizes, int n_in,
                              void* d_out, int out_size) {
    const float* anchor   = (const float*)d_in[0];
    const float* positive = (const float*)d_in[1];
    float* out = (float*)d_out;

    cudaFuncSetAttribute(lse_mma_kernel, cudaFuncAttributeMaxDynamicSharedMemorySize, SMEM_TOTAL);

    prep_kernel<<<NB * ND / 8 / 256, 256>>>(anchor, positive);
    diag_kernel<<<NB / 8, 256>>>(anchor, positive);
    lse_mma_kernel<<<(NB / BM) * 2, 256, SMEM_TOTAL>>>();
    reduce_kernel<<<1, 256>>>(out);
}

// round 9
// speedup vs baseline: 11.7586x; 2.4500x over previous
#include <cuda_runtime.h>
#include <math.h>
#include <stdint.h>

// InfoNCE loss via mma.sync fp16 m16n8k16 (legacy tensor path) + ldmatrix + fused online LSE.
// anchor [8192,512] f32, positive [8192,512] f32 -> scalar f32 mean loss.

#define NB 8192
#define ND 512
#define SCALE 10.0f   // 1/TEMPERATURE

constexpr int BM = 128;          // CTA rows
constexpr int BN = 128;          // CTA cols per j-tile
constexpr int KC = 64;           // k-chunk (halves) = 128B/row => SW128 swizzle
constexpr int NHALF = NB / 2;    // 4096 cols per CTA
constexpr int NT  = NHALF / BN;  // 32 j-tiles
constexpr int CPT = ND / KC;     // 8 k-chunks per tile
constexpr int TOTAL = NT * CPT;  // 256 chunks

constexpr int ATILE = BM * KC * 2;             // 16 KB per operand tile
constexpr int NSTAGE = 4;
constexpr int SMEM_B0 = NSTAGE * ATILE;        // 64 KB
constexpr int SMEM_TOTAL = 2 * SMEM_B0;        // 128 KB

__device__ uint16_t g_Ah[NB * ND];   // fp16-rounded copies (linear layout)
__device__ uint16_t g_Ph[NB * ND];
// 4 partials per row: [halfN(2)][warpCol(2)][row]
__device__ float g_pm[4 * NB];
__device__ float g_ps[4 * NB];
__device__ float g_diag[NB];
__device__ float g_part[32];

// ---------- helpers ----------
__device__ __forceinline__ uint32_t smem_u32(const void* p) {
    uint32_t a;
    asm("{ .reg .u64 t; cvta.to.shared.u64 t, %1; cvt.u32.u64 %0, t; }" : "=r"(a) : "l"(p));
    return a;
}
__device__ __forceinline__ uint64_t gaddr(const void* p) {
    uint64_t a;
    asm("cvta.to.global.u64 %0, %1;" : "=l"(a) : "l"(p));
    return a;
}
__device__ __forceinline__ void cp16(uint32_t dst, uint64_t src) {
    asm volatile("cp.async.cg.shared.global [%0], [%1], 16;" :: "r"(dst), "l"(src));
}
__device__ __forceinline__ void cp_commit() { asm volatile("cp.async.commit_group;" ::: "memory"); }
template <int N> __device__ __forceinline__ void cp_wait() {
    asm volatile("cp.async.wait_group %0;" :: "n"(N) : "memory");
}
__device__ __forceinline__ uint32_t pack_h2(float lo, float hi) {
    uint32_t r;
    asm("cvt.rn.f16x2.f32 %0, %1, %2;" : "=r"(r) : "f"(hi), "f"(lo));
    return r;
}
__device__ __forceinline__ void ldsm4(uint32_t* r, uint32_t addr) {
    asm volatile("ldmatrix.sync.aligned.m8n8.x4.shared.b16 {%0,%1,%2,%3}, [%4];"
                 : "=r"(r[0]), "=r"(r[1]), "=r"(r[2]), "=r"(r[3]) : "r"(addr));
}
// C += A(m16k16,row) * B(k16n8,col), fp16 in / fp32 accum
__device__ __forceinline__ void mma_f16(float* c, const uint32_t* a, const uint32_t* b) {
    asm volatile(
        "mma.sync.aligned.m16n8k16.row.col.f32.f16.f16.f32 "
        "{%0,%1,%2,%3}, {%4,%5,%6,%7}, {%8,%9}, {%0,%1,%2,%3};"
        : "+f"(c[0]), "+f"(c[1]), "+f"(c[2]), "+f"(c[3])
        : "r"(a[0]), "r"(a[1]), "r"(a[2]), "r"(a[3]), "r"(b[0]), "r"(b[1]));
}

// ---------- pre-pass: fp32 -> fp16 (round-to-nearest), linear layout ----------
__global__ void prep_kernel(const float* __restrict__ A, const float* __restrict__ P) {
    int i = blockIdx.x * blockDim.x + threadIdx.x;    // one 8-float group
    if (i >= NB * ND / 8) return;
    float4 a0 = ((const float4*)A)[i * 2], a1 = ((const float4*)A)[i * 2 + 1];
    float4 p0 = ((const float4*)P)[i * 2], p1 = ((const float4*)P)[i * 2 + 1];
    uint4 oa, op;
    oa.x = pack_h2(a0.x, a0.y);
    oa.y = pack_h2(a0.z, a0.w);
    oa.z = pack_h2(a1.x, a1.y);
    oa.w = pack_h2(a1.z, a1.w);
    op.x = pack_h2(p0.x, p0.y);
    op.y = pack_h2(p0.z, p0.w);
    op.z = pack_h2(p1.x, p1.y);
    op.w = pack_h2(p1.z, p1.w);
    ((uint4*)g_Ah)[i] = oa;
    ((uint4*)g_Ph)[i] = op;
}

// ---------- main: fp16 mma GEMM + online logsumexp ----------
__global__ __launch_bounds__(256, 1)
void lse_mma_kernel() {
    extern __shared__ __align__(16) char smem[];
    const uint32_t sbase = smem_u32(smem);
    const int tid  = threadIdx.x;
    const int lane = tid & 31;
    const int w    = tid >> 5;
    const int warpRow = w & 3;     // 4 x 32 rows
    const int warpCol = w >> 2;    // 2 x 64 cols

    const int m0    = (blockIdx.x >> 1) * BM;
    const int halfN = blockIdx.x & 1;
    const int nbase = halfN * NHALF;

    // ---- loader geometry: 2 threads/row, 64B (4 x 16B units) each ----
    const int lr = tid >> 1;            // smem row 0..127
    const int lu = (tid & 1) * 4;       // first of 4 units (8 per 128B row)
    const uint64_t aSrc0 = gaddr(g_Ah) + (uint64_t)(m0 + lr) * (ND * 2) + lu * 16;
    const uint64_t bSrc0 = gaddr(g_Ph) + (uint64_t)(nbase + lr) * (ND * 2) + lu * 16;
    uint32_t aDst[4], bDst[4];
#pragma unroll
    for (int i = 0; i < 4; i++) {
        int u = lu + i;
        int up = u ^ (lr & 7);          // SW128-style 16B-unit swizzle
        aDst[i] = sbase + lr * 128 + up * 16;
        bDst[i] = sbase + SMEM_B0 + lr * 128 + up * 16;
    }

    auto load_chunk = [&](int stage, int chunk) {
        const int jt = chunk >> 3, kc = chunk & 7;
        const uint64_t as = aSrc0 + kc * 128;
        const uint64_t bs = bSrc0 + (uint64_t)jt * (BN * ND * 2) + kc * 128;
        const uint32_t so = stage * ATILE;
#pragma unroll
        for (int i = 0; i < 4; i++) {
            cp16(aDst[i] + so, as + i * 16);
            cp16(bDst[i] + so, bs + i * 16);
        }
        cp_commit();
    };

    load_chunk(0, 0); load_chunk(1, 1); load_chunk(2, 2);

    // ---- ldmatrix lane geometry ----
    const int rr = lane & 7;
    // A x4: tiles (t0: rows+0 u+0, t1: rows+8 u+0, t2: rows+0 u+1, t3: rows+8 u+1)
    const int aT = lane >> 3;                 // 0..3
    uint32_t aRow[2];                         // per mb: this lane's smem row
#pragma unroll
    for (int mb = 0; mb < 2; mb++)
        aRow[mb] = warpRow * 32 + mb * 16 + (aT & 1) * 8 + rr;
    const int aU = aT >> 1;                   // unit offset within k16 (0/1)
    // B x4: tiles (t0: nb0 u+0, t1: nb0 u+1, t2: nb1 u+0, t3: nb1 u+1)
    const int bNb = lane >> 4;                // 0/1 -> nb pair half
    const int bU  = (lane >> 3) & 1;
    uint32_t bRow[4];                         // per j: n-row of this lane
#pragma unroll
    for (int j = 0; j < 4; j++)
        bRow[j] = warpCol * 64 + (2 * j + bNb) * 8 + rr;

    float m_run[4], s_run[4];
#pragma unroll
    for (int i = 0; i < 4; i++) { m_run[i] = -3.0e38f; s_run[i] = 0.0f; }

    float c[2][8][4];

    for (int ch = 0; ch < TOTAL; ch++) {
        const int stage = ch & 3, kc = ch & 7;

        cp_wait<2>();
        __syncthreads();

        if (kc == 0) {
#pragma unroll
            for (int mb = 0; mb < 2; mb++)
#pragma unroll
                for (int nb = 0; nb < 8; nb++)
#pragma unroll
                    for (int q = 0; q < 4; q++) c[mb][nb][q] = 0.0f;
        }

        const uint32_t sA = sbase + stage * ATILE;
        const uint32_t sB = sbase + SMEM_B0 + stage * ATILE;
#pragma unroll
        for (int s = 0; s < 4; s++) {            // 4 k16-steps per chunk
            uint32_t afr[2][4];
#pragma unroll
            for (int mb = 0; mb < 2; mb++) {
                uint32_t u = (uint32_t)(2 * s + aU) ^ (aRow[mb] & 7);
                ldsm4(afr[mb], sA + aRow[mb] * 128 + u * 16);
            }
#pragma unroll
            for (int j = 0; j < 4; j++) {
                uint32_t bfr[4];
                uint32_t u = (uint32_t)(2 * s + bU) ^ (bRow[j] & 7);
                ldsm4(bfr, sB + bRow[j] * 128 + u * 16);
#pragma unroll
                for (int h = 0; h < 2; h++)
#pragma unroll
                    for (int mb = 0; mb < 2; mb++)
                        mma_f16(c[mb][2 * j + h], afr[mb], bfr + h * 2);
            }
        }

        // prefetch chunk ch+3 (stage consumed in iter ch-1; sync above protects)
        if (ch + 3 < TOTAL) load_chunk((ch + 3) & 3, ch + 3);
        else cp_commit();   // keep group count uniform

        // ---- register-only online-LSE epilogue at tile end ----
        if (kc == 7) {
#pragma unroll
            for (int ri = 0; ri < 4; ri++) {
                const int mb = ri >> 1, hh = ri & 1;
                float v[16];
#pragma unroll
                for (int nb = 0; nb < 8; nb++) {
                    v[2 * nb]     = c[mb][nb][hh * 2];
                    v[2 * nb + 1] = c[mb][nb][hh * 2 + 1];
                }
                float mx = v[0];
#pragma unroll
                for (int i = 1; i < 16; i++) mx = fmaxf(mx, v[i]);
                mx *= SCALE;
                // exp-skip: tiles far below the running max contribute < e^-30
                if (mx >= m_run[ri] - 30.0f) {
                    const float mn = fmaxf(m_run[ri], mx);
                    float sa = 0.0f;
#pragma unroll
                    for (int i = 0; i < 16; i++) sa += __expf(fmaf(v[i], SCALE, -mn));
                    s_run[ri] = s_run[ri] * __expf(m_run[ri] - mn) + sa;
                    m_run[ri] = mn;
                }
            }
        }
    }

    // merge (m,s) across the 4-lane column group; write per-(halfN, warpCol) partials
    const int qr = lane >> 2;
#pragma unroll
    for (int ri = 0; ri < 4; ri++) {
        float m = m_run[ri], s = s_run[ri];
#pragma unroll
        for (int off = 1; off < 4; off <<= 1) {
            float mo = __shfl_xor_sync(0xffffffffu, m, off);
            float so = __shfl_xor_sync(0xffffffffu, s, off);
            float mn = fmaxf(m, mo);
            s = s * __expf(m - mn) + so * __expf(mo - mn);
            m = mn;
        }
        if ((lane & 3) == 0) {
            const int mb = ri >> 1, hh = ri & 1;
            const int row = m0 + warpRow * 32 + mb * 16 + hh * 8 + qr;
            const int slot = halfN * 2 + warpCol;
            g_pm[slot * NB + row] = m;
            g_ps[slot * NB + row] = s;
        }
    }
}

// diag[i] = <anchor_i, positive_i> * SCALE — full fp32 (matches reference)
__global__ void diag_kernel(const float* __restrict__ A, const float* __restrict__ P) {
    int warp = (blockIdx.x * blockDim.x + threadIdx.x) >> 5;
    int lane = threadIdx.x & 31;
    if (warp >= NB) return;
    const float4* a4 = (const float4*)(A + (size_t)warp * ND);
    const float4* p4 = (const float4*)(P + (size_t)warp * ND);
    float s = 0.0f;
#pragma unroll
    for (int i = 0; i < 4; i++) {
        float4 a = a4[i * 32 + lane];
        float4 p = p4[i * 32 + lane];
        s += a.x * p.x + a.y * p.y + a.z * p.z + a.w * p.w;
    }
#pragma unroll
    for (int off = 16; off; off >>= 1) s += __shfl_xor_sync(0xffffffffu, s, off);
    if (lane == 0) g_diag[warp] = s * SCALE;
}

// stage 1: 32 blocks x 256 threads, one row each -> g_part[32]
__global__ void reduce1_kernel() {
    __shared__ float red[256];
    const int i = blockIdx.x * 256 + threadIdx.x;   // 8192 rows exactly
    float m = g_pm[i];
#pragma unroll
    for (int q = 1; q < 4; q++) m = fmaxf(m, g_pm[q * NB + i]);
    float se = 0.0f;
#pragma unroll
    for (int q = 0; q < 4; q++) se += g_ps[q * NB + i] * __expf(g_pm[q * NB + i] - m);
    red[threadIdx.x] = m + logf(se) - g_diag[i];
    __syncthreads();
    for (int st = 128; st; st >>= 1) {
        if (threadIdx.x < st) red[threadIdx.x] += red[threadIdx.x + st];
        __syncthreads();
    }
    if (threadIdx.x == 0) g_part[blockIdx.x] = red[0];
}

__global__ void reduce2_kernel(float* __restrict__ out) {
    float s = g_part[threadIdx.x];   // 32 threads
#pragma unroll
    for (int off = 16; off; off >>= 1) s += __shfl_xor_sync(0xffffffffu, s, off);
    if (threadIdx.x == 0) out[0] = s / (float)NB;
}

extern "C" void kernel_launch(void* const* d_in, const int* in_sizes, int n_in,
                              void* d_out, int out_size) {
    const float* anchor   = (const float*)d_in[0];
    const float* positive = (const float*)d_in[1];
    float* out = (float*)d_out;

    cudaFuncSetAttribute(lse_mma_kernel, cudaFuncAttributeMaxDynamicSharedMemorySize, SMEM_TOTAL);

    prep_kernel<<<NB * ND / 8 / 256, 256>>>(anchor, positive);
    diag_kernel<<<NB / 8, 256>>>(anchor, positive);
    lse_mma_kernel<<<(NB / BM) * 2, 256, SMEM_TOTAL>>>();
    reduce1_kernel<<<32, 256>>>();
    reduce2_kernel<<<1, 32>>>(out);
}

// round 10
// speedup vs baseline: 13.1214x; 1.1159x over previous
#include <cuda_runtime.h>
#include <math.h>
#include <stdint.h>

// InfoNCE loss via mma.sync fp16 m16n8k16 + ldmatrix + fused online LSE.
// R10: 512 threads/CTA (4 warps/SMSP) for latency hiding; fused reduce.
// anchor [8192,512] f32, positive [8192,512] f32 -> scalar f32 mean loss.

#define NB 8192
#define ND 512
#define SCALE 10.0f   // 1/TEMPERATURE

constexpr int BM = 128;          // CTA rows
constexpr int BN = 128;          // CTA cols per j-tile
constexpr int KC = 64;           // k-chunk (halves) = 128B/row
constexpr int NHALF = NB / 2;    // 4096 cols per CTA
constexpr int NT  = NHALF / BN;  // 32 j-tiles
constexpr int CPT = ND / KC;     // 8 k-chunks per tile
constexpr int TOTAL = NT * CPT;  // 256 chunks

constexpr int ATILE = BM * KC * 2;             // 16 KB per operand tile
constexpr int NSTAGE = 4;
constexpr int SMEM_B0 = NSTAGE * ATILE;        // 64 KB
constexpr int SMEM_TOTAL = 2 * SMEM_B0;        // 128 KB
constexpr int NTHR = 512;

__device__ uint16_t g_Ah[NB * ND];   // fp16-rounded copies
__device__ uint16_t g_Ph[NB * ND];
// 8 partials per row: [halfN(2)][warpCol(4)][row]
__device__ float g_pm[8 * NB];
__device__ float g_ps[8 * NB];
__device__ float g_diag[NB];

// ---------- helpers ----------
__device__ __forceinline__ uint32_t smem_u32(const void* p) {
    uint32_t a;
    asm("{ .reg .u64 t; cvta.to.shared.u64 t, %1; cvt.u32.u64 %0, t; }" : "=r"(a) : "l"(p));
    return a;
}
__device__ __forceinline__ uint64_t gaddr(const void* p) {
    uint64_t a;
    asm("cvta.to.global.u64 %0, %1;" : "=l"(a) : "l"(p));
    return a;
}
__device__ __forceinline__ void cp16(uint32_t dst, uint64_t src) {
    asm volatile("cp.async.cg.shared.global [%0], [%1], 16;" :: "r"(dst), "l"(src));
}
__device__ __forceinline__ void cp_commit() { asm volatile("cp.async.commit_group;" ::: "memory"); }
template <int N> __device__ __forceinline__ void cp_wait() {
    asm volatile("cp.async.wait_group %0;" :: "n"(N) : "memory");
}
__device__ __forceinline__ uint32_t pack_h2(float lo, float hi) {
    uint32_t r;
    asm("cvt.rn.f16x2.f32 %0, %1, %2;" : "=r"(r) : "f"(hi), "f"(lo));
    return r;
}
__device__ __forceinline__ void ldsm4(uint32_t* r, uint32_t addr) {
    asm volatile("ldmatrix.sync.aligned.m8n8.x4.shared.b16 {%0,%1,%2,%3}, [%4];"
                 : "=r"(r[0]), "=r"(r[1]), "=r"(r[2]), "=r"(r[3]) : "r"(addr));
}
__device__ __forceinline__ void mma_f16(float* c, const uint32_t* a, const uint32_t* b) {
    asm volatile(
        "mma.sync.aligned.m16n8k16.row.col.f32.f16.f16.f32 "
        "{%0,%1,%2,%3}, {%4,%5,%6,%7}, {%8,%9}, {%0,%1,%2,%3};"
        : "+f"(c[0]), "+f"(c[1]), "+f"(c[2]), "+f"(c[3])
        : "r"(a[0]), "r"(a[1]), "r"(a[2]), "r"(a[3]), "r"(b[0]), "r"(b[1]));
}

// ---------- pre-pass: fp32 -> fp16 round-to-nearest ----------
__global__ void prep_kernel(const float* __restrict__ A, const float* __restrict__ P) {
    int i = blockIdx.x * blockDim.x + threadIdx.x;    // one 8-float group
    if (i >= NB * ND / 8) return;
    float4 a0 = ((const float4*)A)[i * 2], a1 = ((const float4*)A)[i * 2 + 1];
    float4 p0 = ((const float4*)P)[i * 2], p1 = ((const float4*)P)[i * 2 + 1];
    uint4 oa, op;
    oa.x = pack_h2(a0.x, a0.y);
    oa.y = pack_h2(a0.z, a0.w);
    oa.z = pack_h2(a1.x, a1.y);
    oa.w = pack_h2(a1.z, a1.w);
    op.x = pack_h2(p0.x, p0.y);
    op.y = pack_h2(p0.z, p0.w);
    op.z = pack_h2(p1.x, p1.y);
    op.w = pack_h2(p1.z, p1.w);
    ((uint4*)g_Ah)[i] = oa;
    ((uint4*)g_Ph)[i] = op;
}

// ---------- main: fp16 mma GEMM + online logsumexp ----------
__global__ __launch_bounds__(NTHR, 1)
void lse_mma_kernel() {
    extern __shared__ __align__(16) char smem[];
    const uint32_t sbase = smem_u32(smem);
    const int tid  = threadIdx.x;
    const int lane = tid & 31;
    const int w    = tid >> 5;         // 0..15
    const int warpRow = w & 3;         // 4 x 32 rows
    const int warpCol = w >> 2;        // 4 x 32 cols

    const int m0    = (blockIdx.x >> 1) * BM;
    const int halfN = blockIdx.x & 1;
    const int nbase = halfN * NHALF;

    // ---- loader geometry: 4 threads/row, 32B (2 x 16B units) each ----
    const int lr = tid >> 2;            // smem row 0..127
    const int lu = (tid & 3) * 2;       // first of 2 units (8 per 128B row)
    const uint64_t aSrc0 = gaddr(g_Ah) + (uint64_t)(m0 + lr) * (ND * 2) + lu * 16;
    const uint64_t bSrc0 = gaddr(g_Ph) + (uint64_t)(nbase + lr) * (ND * 2) + lu * 16;
    uint32_t aDst[2], bDst[2];
#pragma unroll
    for (int i = 0; i < 2; i++) {
        int u = lu + i;
        int up = u ^ (lr & 7);          // 16B-unit swizzle
        aDst[i] = sbase + lr * 128 + up * 16;
        bDst[i] = sbase + SMEM_B0 + lr * 128 + up * 16;
    }

    auto load_chunk = [&](int stage, int chunk) {
        const int jt = chunk >> 3, kc = chunk & 7;
        const uint64_t as = aSrc0 + kc * 128;
        const uint64_t bs = bSrc0 + (uint64_t)jt * (BN * ND * 2) + kc * 128;
        const uint32_t so = stage * ATILE;
#pragma unroll
        for (int i = 0; i < 2; i++) {
            cp16(aDst[i] + so, as + i * 16);
            cp16(bDst[i] + so, bs + i * 16);
        }
        cp_commit();
    };

    load_chunk(0, 0); load_chunk(1, 1); load_chunk(2, 2);

    // ---- ldmatrix lane geometry ----
    const int rr = lane & 7;
    const int aT = lane >> 3;                 // A x4 tile id
    uint32_t aRow[2];
#pragma unroll
    for (int mb = 0; mb < 2; mb++)
        aRow[mb] = warpRow * 32 + mb * 16 + (aT & 1) * 8 + rr;
    const int aU = aT >> 1;
    const int bNb = lane >> 4;                // n8 parity within pair
    const int bU  = (lane >> 3) & 1;
    uint32_t bRow[2];
#pragma unroll
    for (int j = 0; j < 2; j++)
        bRow[j] = warpCol * 32 + (2 * j + bNb) * 8 + rr;

    float m_run[4], s_run[4];
#pragma unroll
    for (int i = 0; i < 4; i++) { m_run[i] = -3.0e38f; s_run[i] = 0.0f; }

    float c[2][4][4];

    for (int ch = 0; ch < TOTAL; ch++) {
        const int stage = ch & 3, kc = ch & 7;

        cp_wait<2>();
        __syncthreads();

        if (kc == 0) {
#pragma unroll
            for (int mb = 0; mb < 2; mb++)
#pragma unroll
                for (int nb = 0; nb < 4; nb++)
#pragma unroll
                    for (int q = 0; q < 4; q++) c[mb][nb][q] = 0.0f;
        }

        const uint32_t sA = sbase + stage * ATILE;
        const uint32_t sB = sbase + SMEM_B0 + stage * ATILE;
#pragma unroll
        for (int s = 0; s < 4; s++) {            // 4 k16-steps per chunk
            uint32_t afr[2][4];
#pragma unroll
            for (int mb = 0; mb < 2; mb++) {
                uint32_t u = (uint32_t)(2 * s + aU) ^ (aRow[mb] & 7);
                ldsm4(afr[mb], sA + aRow[mb] * 128 + u * 16);
            }
#pragma unroll
            for (int j = 0; j < 2; j++) {
                uint32_t bfr[4];
                uint32_t u = (uint32_t)(2 * s + bU) ^ (bRow[j] & 7);
                ldsm4(bfr, sB + bRow[j] * 128 + u * 16);
#pragma unroll
                for (int h = 0; h < 2; h++)
#pragma unroll
                    for (int mb = 0; mb < 2; mb++)
                        mma_f16(c[mb][2 * j + h], afr[mb], bfr + h * 2);
            }
        }

        // prefetch chunk ch+3
        if (ch + 3 < TOTAL) load_chunk((ch + 3) & 3, ch + 3);
        else cp_commit();   // keep group count uniform

        // ---- register-only online-LSE epilogue at tile end ----
        if (kc == 7) {
#pragma unroll
            for (int ri = 0; ri < 4; ri++) {
                const int mb = ri >> 1, hh = ri & 1;
                float v[8];
#pragma unroll
                for (int nb = 0; nb < 4; nb++) {
                    v[2 * nb]     = c[mb][nb][hh * 2];
                    v[2 * nb + 1] = c[mb][nb][hh * 2 + 1];
                }
                float mx = v[0];
#pragma unroll
                for (int i = 1; i < 8; i++) mx = fmaxf(mx, v[i]);
                mx *= SCALE;
                // exp-skip: tiles far below the running max contribute < e^-30
                if (mx >= m_run[ri] - 30.0f) {
                    const float mn = fmaxf(m_run[ri], mx);
                    float sa = 0.0f;
#pragma unroll
                    for (int i = 0; i < 8; i++) sa += __expf(fmaf(v[i], SCALE, -mn));
                    s_run[ri] = s_run[ri] * __expf(m_run[ri] - mn) + sa;
                    m_run[ri] = mn;
                }
            }
        }
    }

    // merge (m,s) across the 4-lane column group; write per-(halfN, warpCol) partials
    const int qr = lane >> 2;
#pragma unroll
    for (int ri = 0; ri < 4; ri++) {
        float m = m_run[ri], s = s_run[ri];
#pragma unroll
        for (int off = 1; off < 4; off <<= 1) {
            float mo = __shfl_xor_sync(0xffffffffu, m, off);
            float so = __shfl_xor_sync(0xffffffffu, s, off);
            float mn = fmaxf(m, mo);
            s = s * __expf(m - mn) + so * __expf(mo - mn);
            m = mn;
        }
        if ((lane & 3) == 0) {
            const int mb = ri >> 1, hh = ri & 1;
            const int row = m0 + warpRow * 32 + mb * 16 + hh * 8 + qr;
            const int slot = halfN * 4 + warpCol;      // 8 distinct slots per row
            g_pm[slot * NB + row] = m;
            g_ps[slot * NB + row] = s;
        }
    }
}

// diag[i] = <anchor_i, positive_i> * SCALE — full fp32 (matches reference)
__global__ void diag_kernel(const float* __restrict__ A, const float* __restrict__ P) {
    int warp = (blockIdx.x * blockDim.x + threadIdx.x) >> 5;
    int lane = threadIdx.x & 31;
    if (warp >= NB) return;
    const float4* a4 = (const float4*)(A + (size_t)warp * ND);
    const float4* p4 = (const float4*)(P + (size_t)warp * ND);
    float s = 0.0f;
#pragma unroll
    for (int i = 0; i < 4; i++) {
        float4 a = a4[i * 32 + lane];
        float4 p = p4[i * 32 + lane];
        s += a.x * p.x + a.y * p.y + a.z * p.z + a.w * p.w;
    }
#pragma unroll
    for (int off = 16; off; off >>= 1) s += __shfl_xor_sync(0xffffffffu, s, off);
    if (lane == 0) g_diag[warp] = s * SCALE;
}

// fused final reduce: one 1024-thread block
__global__ void reduce_kernel(float* __restrict__ out) {
    __shared__ float red[1024];
    float s = 0.0f;
    for (int i = threadIdx.x; i < NB; i += 1024) {
        float m = g_pm[i];
#pragma unroll
        for (int q = 1; q < 8; q++) m = fmaxf(m, g_pm[q * NB + i]);
        float se = 0.0f;
#pragma unroll
        for (int q = 0; q < 8; q++) se += g_ps[q * NB + i] * __expf(g_pm[q * NB + i] - m);
        s += m + logf(se) - g_diag[i];
    }
    red[threadIdx.x] = s;
    __syncthreads();
    for (int st = 512; st; st >>= 1) {
        if (threadIdx.x < st) red[threadIdx.x] += red[threadIdx.x + st];
        __syncthreads();
    }
    if (threadIdx.x == 0) out[0] = red[0] / (float)NB;
}

extern "C" void kernel_launch(void* const* d_in, const int* in_sizes, int n_in,
                              void* d_out, int out_size) {
    const float* anchor   = (const float*)d_in[0];
    const float* positive = (const float*)d_in[1];
    float* out = (float*)d_out;

    cudaFuncSetAttribute(lse_mma_kernel, cudaFuncAttributeMaxDynamicSharedMemorySize, SMEM_TOTAL);

    prep_kernel<<<NB * ND / 8 / 256, 256>>>(anchor, positive);
    diag_kernel<<<NB / 8, 256>>>(anchor, positive);
    lse_mma_kernel<<<(NB / BM) * 2, NTHR, SMEM_TOTAL>>>();
    reduce_kernel<<<1, 1024>>>(out);
}